// round 4
// baseline (speedup 1.0000x reference)
#include <cuda_runtime.h>
#include <cuda_bf16.h>

// GraphSAGE, 2-layer, mean aggregation.
//   h1  = relu(mean_agg(x) @ W1_l + b1 + x @ W1_r)
//   out = mean_agg(h1) @ W2_l + b2 + h1 @ W2_r
// Key transforms:
//   - layer-2 is 64->1, so mean_agg(h1)@W2_l == mean_agg(h1@W2_l): aggregate
//     SCALARS; h1 never materialized (s,r computed in layer-1 accumulators).
//   - layer-1 aggregation via per-call CSR (counting sort) -> gather-sum with
//     NO float atomics.
//   - edge_index dtype (int32 vs int64) detected on-device: JAX with default
//     x64-disabled silently downcasts the reference's int64 to int32.

#define MAXN 100000
#define MAXE 1600000
#define F 64            // NFEAT == NHID == 64

// ---- device scratch (static; allocation is forbidden) ----
__device__ int g_is64;
__device__ int g_deg[MAXN];
__device__ int g_rowstart[MAXN + 1];
__device__ int g_cursor[MAXN];
__device__ int g_csr[MAXE];
__device__ __align__(16) float g_agg1[(size_t)MAXN * F];
__device__ float g_s[MAXN];
__device__ float g_r[MAXN];

// ---------------------------------------------------------------------------
// Detect edge_index dtype. Interpreted as int32: if the buffer is really
// int64 (little-endian, values < 2^31) every odd word is 0. If int32, odd
// words are random node ids (OR over 256 of them is nonzero w.p. ~1).
__global__ void detect_kernel(const int* __restrict__ ei) {
    int tid = threadIdx.x;
    int nz = 0;
    for (int j = tid; j < 256; j += 32) nz |= ei[2 * j + 1];
    #pragma unroll
    for (int d = 16; d; d >>= 1) nz |= __shfl_xor_sync(0xffffffffu, nz, d);
    if (tid == 0) g_is64 = (nz == 0) ? 1 : 0;
}

__device__ __forceinline__ int edge_val(const int* __restrict__ ei,
                                        int is64, int pos) {
    // pos is the logical element index into the [2*E] edge array.
    return is64 ? ei[2 * pos] : ei[pos];
}

__global__ void zero_deg_kernel(int n) {
    int i = blockIdx.x * blockDim.x + threadIdx.x;
    if (i < n) g_deg[i] = 0;
}

__global__ void count_kernel(const int* __restrict__ ei, int e, int n) {
    int idx = blockIdx.x * blockDim.x + threadIdx.x;
    if (idx >= e) return;
    int is64 = g_is64;
    int d = edge_val(ei, is64, e + idx);   // dst[idx]
    if ((unsigned)d < (unsigned)n) atomicAdd(&g_deg[d], 1);
}

// Single-block exclusive scan over g_deg -> g_rowstart / g_cursor.
// 1024 threads, 4 items/thread per chunk (4096 per iteration, ~25 iters).
__global__ void scan_kernel(int n) {
    __shared__ int wsum[32];
    __shared__ int s_carry;
    const int tid = threadIdx.x, lane = tid & 31, wid = tid >> 5;
    if (tid == 0) s_carry = 0;
    __syncthreads();

    for (int base = 0; base < n; base += 4096) {
        int i0 = base + tid * 4;
        int v0 = (i0 + 0 < n) ? g_deg[i0 + 0] : 0;
        int v1 = (i0 + 1 < n) ? g_deg[i0 + 1] : 0;
        int v2 = (i0 + 2 < n) ? g_deg[i0 + 2] : 0;
        int v3 = (i0 + 3 < n) ? g_deg[i0 + 3] : 0;
        int tsum = v0 + v1 + v2 + v3;

        int xs = tsum;
        #pragma unroll
        for (int d = 1; d < 32; d <<= 1) {
            int t = __shfl_up_sync(0xffffffffu, xs, d);
            if (lane >= d) xs += t;
        }
        if (lane == 31) wsum[wid] = xs;
        __syncthreads();
        if (wid == 0) {
            int w = wsum[lane];
            #pragma unroll
            for (int d = 1; d < 32; d <<= 1) {
                int t = __shfl_up_sync(0xffffffffu, w, d);
                if (lane >= d) w += t;
            }
            wsum[lane] = w;  // inclusive across warps
        }
        __syncthreads();
        int warp_off = (wid == 0) ? 0 : wsum[wid - 1];
        int carry = s_carry;
        int excl = carry + warp_off + xs - tsum;

        int e0 = excl;
        int e1 = e0 + v0;
        int e2 = e1 + v1;
        int e3 = e2 + v2;
        if (i0 + 0 < n) { g_rowstart[i0 + 0] = e0; g_cursor[i0 + 0] = e0; }
        if (i0 + 1 < n) { g_rowstart[i0 + 1] = e1; g_cursor[i0 + 1] = e1; }
        if (i0 + 2 < n) { g_rowstart[i0 + 2] = e2; g_cursor[i0 + 2] = e2; }
        if (i0 + 3 < n) { g_rowstart[i0 + 3] = e3; g_cursor[i0 + 3] = e3; }
        __syncthreads();
        if (tid == 1023) s_carry = carry + wsum[31];
        __syncthreads();
    }
    if (tid == 0) g_rowstart[n] = s_carry;
}

__global__ void fill_kernel(const int* __restrict__ ei, int e, int n) {
    int idx = blockIdx.x * blockDim.x + threadIdx.x;
    if (idx >= e) return;
    int is64 = g_is64;
    int d = edge_val(ei, is64, e + idx);   // dst[idx]
    int s = edge_val(ei, is64, idx);       // src[idx]
    if ((unsigned)d < (unsigned)n && (unsigned)s < (unsigned)n) {
        int pos = atomicAdd(&g_cursor[d], 1);
        g_csr[pos] = s;
    }
}

// Half-warp (16 lanes, one float4 each) per node: gather-sum x rows over the
// node's in-edges, write mean. No atomics; csr index is a broadcast load.
__global__ void agg1_kernel(const float* __restrict__ x, int n) {
    int gt = blockIdx.x * blockDim.x + threadIdx.x;
    int node = gt >> 4;
    int q = gt & 15;
    if (node >= n) return;
    int beg = g_rowstart[node];
    int end = g_rowstart[node + 1];
    const float4* __restrict__ x4 = (const float4*)x;
    float4 acc = make_float4(0.f, 0.f, 0.f, 0.f);
    for (int j = beg; j < end; j++) {
        int s = g_csr[j];
        float4 v = x4[(size_t)s * 16 + q];
        acc.x += v.x; acc.y += v.y; acc.z += v.z; acc.w += v.w;
    }
    int deg = end - beg;
    float inv = 1.0f / (float)(deg > 0 ? deg : 1);
    acc.x *= inv; acc.y *= inv; acc.z *= inv; acc.w *= inv;
    ((float4*)g_agg1)[(size_t)node * 16 + q] = acc;
}

// One thread per node: h1 row in 64 accumulator registers, then collapse to
// s = relu(h1).W2_l and r = relu(h1).W2_r immediately (h1 never stored).
__global__ __launch_bounds__(128) void h1_kernel(
    const float* __restrict__ x,
    const float* __restrict__ W1l, const float* __restrict__ b1,
    const float* __restrict__ W1r,
    const float* __restrict__ W2l, const float* __restrict__ W2r,
    int n) {
    __shared__ __align__(16) float sWl[F * F];
    __shared__ __align__(16) float sWr[F * F];
    __shared__ float sb1[F], sW2l[F], sW2r[F];
    for (int idx = threadIdx.x; idx < F * F; idx += blockDim.x) {
        sWl[idx] = W1l[idx];
        sWr[idx] = W1r[idx];
    }
    if (threadIdx.x < F) {
        sb1[threadIdx.x]  = b1[threadIdx.x];
        sW2l[threadIdx.x] = W2l[threadIdx.x];
        sW2r[threadIdx.x] = W2r[threadIdx.x];
    }
    __syncthreads();

    int i = blockIdx.x * blockDim.x + threadIdx.x;
    if (i >= n) return;

    float acc[F];
    #pragma unroll
    for (int j = 0; j < F; j++) acc[j] = sb1[j];

    const float4* __restrict__ ag4 = ((const float4*)g_agg1) + (size_t)i * 16;
    const float4* __restrict__ xx4 = ((const float4*)x) + (size_t)i * 16;

    #pragma unroll 1
    for (int kc = 0; kc < 16; kc++) {
        float4 a4 = ag4[kc];
        float4 b4 = xx4[kc];
        float av[4] = {a4.x, a4.y, a4.z, a4.w};
        float xv[4] = {b4.x, b4.y, b4.z, b4.w};
        #pragma unroll
        for (int kk = 0; kk < 4; kk++) {
            int k = kc * 4 + kk;
            const float4* wl4 = (const float4*)&sWl[k * F];
            const float4* wr4 = (const float4*)&sWr[k * F];
            #pragma unroll
            for (int j4 = 0; j4 < 16; j4++) {
                float4 wl = wl4[j4];
                float4 wr = wr4[j4];
                acc[j4 * 4 + 0] += av[kk] * wl.x + xv[kk] * wr.x;
                acc[j4 * 4 + 1] += av[kk] * wl.y + xv[kk] * wr.y;
                acc[j4 * 4 + 2] += av[kk] * wl.z + xv[kk] * wr.z;
                acc[j4 * 4 + 3] += av[kk] * wl.w + xv[kk] * wr.w;
            }
        }
    }

    float s = 0.f, r = 0.f;
    #pragma unroll
    for (int j = 0; j < F; j++) {
        float h = fmaxf(acc[j], 0.f);
        s += h * sW2l[j];
        r += h * sW2r[j];
    }
    g_s[i] = s;
    g_r[i] = r;
}

// One thread per node: out[i] = mean_j s[j] + b2 + r[i]
__global__ void out_kernel(const float* __restrict__ b2,
                           float* __restrict__ out, int n) {
    int i = blockIdx.x * blockDim.x + threadIdx.x;
    if (i >= n) return;
    int beg = g_rowstart[i];
    int end = g_rowstart[i + 1];
    float sum = 0.f;
    for (int j = beg; j < end; j++) sum += g_s[g_csr[j]];
    int deg = end - beg;
    float inv = 1.0f / (float)(deg > 0 ? deg : 1);
    out[i] = sum * inv + b2[0] + g_r[i];
}

// ---------------------------------------------------------------------------
extern "C" void kernel_launch(void* const* d_in, const int* in_sizes, int n_in,
                              void* d_out, int out_size) {
    const float* x   = (const float*)d_in[0];
    const int*   ei  = (const int*)d_in[1];   // int32 OR int64 (detected on device)
    const float* W1l = (const float*)d_in[2];
    const float* b1  = (const float*)d_in[3];
    const float* W1r = (const float*)d_in[4];
    const float* W2l = (const float*)d_in[5];
    const float* b2  = (const float*)d_in[6];
    const float* W2r = (const float*)d_in[7];
    float* out = (float*)d_out;

    int n = in_sizes[0] / F;      // 100000
    int e = in_sizes[1] / 2;      // 1600000

    detect_kernel<<<1, 32>>>(ei);
    zero_deg_kernel<<<(n + 255) / 256, 256>>>(n);
    count_kernel<<<(e + 255) / 256, 256>>>(ei, e, n);
    scan_kernel<<<1, 1024>>>(n);
    fill_kernel<<<(e + 255) / 256, 256>>>(ei, e, n);
    agg1_kernel<<<(n * 16 + 255) / 256, 256>>>(x, n);
    h1_kernel<<<(n + 127) / 128, 128>>>(x, W1l, b1, W1r, W2l, W2r, n);
    out_kernel<<<(n + 255) / 256, 256>>>(b2, out, n);
}

// round 5
// speedup vs baseline: 1.8431x; 1.8431x over previous
#include <cuda_runtime.h>
#include <cuda_bf16.h>

// GraphSAGE, 2-layer, mean aggregation.
//   h1  = relu(mean_agg(x) @ W1_l + b1 + x @ W1_r)
//   out = mean_agg(h1) @ W2_l + b2 + h1 @ W2_r
// Transforms:
//   - layer-2 is 64->1: aggregate SCALARS (s = relu(h1).W2_l per node); h1
//     never materialized.
//   - layer-1 aggregation via per-call CSR (counting sort) -> gather-sum, no
//     float atomics.
//   - multi-block 3-phase scan (R4 ncu: single-block scan was 76us, issue=12%).
//   - h1 GEMM uses packed fma.rn.f32x2 (FFMA2) + 2 nodes/thread to amortize
//     shared-weight LDS.
//   - edge_index dtype (int32 vs int64) detected on-device.

#define MAXN 100000
#define MAXE 1600000
#define F 64
#define SCAN_CHUNK 4096
#define MAX_BLOCKS_SCAN 32   // ceil(MAXN/4096)=25 <= 32 (one warp scans bsums)

typedef unsigned long long ull;

// ---- device scratch (static; allocation is forbidden) ----
__device__ int g_is64;
__device__ int g_deg[MAXN];
__device__ int g_rowstart[MAXN + 1];
__device__ int g_cursor[MAXN];
__device__ int g_csr[MAXE];
__device__ int g_bsum[MAX_BLOCKS_SCAN];
__device__ int g_boff[MAX_BLOCKS_SCAN];
__device__ __align__(16) float g_agg1[(size_t)MAXN * F];
__device__ float g_s[MAXN];
__device__ float g_r[MAXN];

// ---- packed f32x2 helpers -------------------------------------------------
__device__ __forceinline__ ull pk2(float v) {
    ull r;
    asm("mov.b64 %0, {%1, %1};" : "=l"(r) : "f"(v));
    return r;
}
__device__ __forceinline__ ull fma2(ull a, ull b, ull c) {
    ull d;
    asm("fma.rn.f32x2 %0, %1, %2, %3;" : "=l"(d) : "l"(a), "l"(b), "l"(c));
    return d;
}
__device__ __forceinline__ void upk2(ull v, float& lo, float& hi) {
    asm("mov.b64 {%0, %1}, %2;" : "=f"(lo), "=f"(hi) : "l"(v));
}

// ---------------------------------------------------------------------------
// Detect edge_index dtype: viewed as int32, an int64 buffer (values < 2^31)
// has all odd words zero; an int32 buffer has random node ids there.
__global__ void detect_kernel(const int* __restrict__ ei) {
    int tid = threadIdx.x;
    int nz = 0;
    for (int j = tid; j < 256; j += 32) nz |= ei[2 * j + 1];
    #pragma unroll
    for (int d = 16; d; d >>= 1) nz |= __shfl_xor_sync(0xffffffffu, nz, d);
    if (tid == 0) g_is64 = (nz == 0) ? 1 : 0;
}

__device__ __forceinline__ int edge_val(const int* __restrict__ ei,
                                        int is64, int pos) {
    return is64 ? ei[2 * pos] : ei[pos];
}

__global__ void zero_deg_kernel(int n) {
    int i = blockIdx.x * blockDim.x + threadIdx.x;
    if (i < n) g_deg[i] = 0;
}

__global__ void count_kernel(const int* __restrict__ ei, int e, int n) {
    int idx = blockIdx.x * blockDim.x + threadIdx.x;
    if (idx >= e) return;
    int is64 = g_is64;
    int d = edge_val(ei, is64, e + idx);   // dst[idx]
    if ((unsigned)d < (unsigned)n) atomicAdd(&g_deg[d], 1);
}

// ---- 3-phase scan ---------------------------------------------------------
// Phase A: per-block sum of a 4096-item chunk of g_deg.
__global__ void scanA_kernel(int n) {
    __shared__ int wsum[32];
    const int tid = threadIdx.x, lane = tid & 31, wid = tid >> 5;
    int i0 = blockIdx.x * SCAN_CHUNK + tid * 4;
    int s = 0;
    if (i0 + 3 < n) {
        int4 v = *(const int4*)&g_deg[i0];
        s = v.x + v.y + v.z + v.w;
    } else {
        for (int j = 0; j < 4; j++) if (i0 + j < n) s += g_deg[i0 + j];
    }
    #pragma unroll
    for (int d = 16; d; d >>= 1) s += __shfl_xor_sync(0xffffffffu, s, d);
    if (lane == 0) wsum[wid] = s;
    __syncthreads();
    if (wid == 0) {
        int w = wsum[lane];
        #pragma unroll
        for (int d = 16; d; d >>= 1) w += __shfl_xor_sync(0xffffffffu, w, d);
        if (lane == 0) g_bsum[blockIdx.x] = w;
    }
}

// Phase B: one warp exclusive-scans the (<=32) block sums.
__global__ void scanB_kernel(int nb, int n) {
    int lane = threadIdx.x;
    int v = (lane < nb) ? g_bsum[lane] : 0;
    int x = v;
    #pragma unroll
    for (int d = 1; d < 32; d <<= 1) {
        int t = __shfl_up_sync(0xffffffffu, x, d);
        if (lane >= d) x += t;
    }
    if (lane < nb) g_boff[lane] = x - v;   // exclusive
    if (lane == 31) g_rowstart[n] = x;     // total
}

// Phase C: per-block exclusive scan of its chunk, plus block offset.
__global__ void scanC_kernel(int n) {
    __shared__ int wsum[32];
    const int tid = threadIdx.x, lane = tid & 31, wid = tid >> 5;
    int base = blockIdx.x * SCAN_CHUNK;
    int i0 = base + tid * 4;
    int v0 = (i0 + 0 < n) ? g_deg[i0 + 0] : 0;
    int v1 = (i0 + 1 < n) ? g_deg[i0 + 1] : 0;
    int v2 = (i0 + 2 < n) ? g_deg[i0 + 2] : 0;
    int v3 = (i0 + 3 < n) ? g_deg[i0 + 3] : 0;
    int tsum = v0 + v1 + v2 + v3;

    int xs = tsum;
    #pragma unroll
    for (int d = 1; d < 32; d <<= 1) {
        int t = __shfl_up_sync(0xffffffffu, xs, d);
        if (lane >= d) xs += t;
    }
    if (lane == 31) wsum[wid] = xs;
    __syncthreads();
    if (wid == 0) {
        int w = wsum[lane];
        #pragma unroll
        for (int d = 1; d < 32; d <<= 1) {
            int t = __shfl_up_sync(0xffffffffu, w, d);
            if (lane >= d) w += t;
        }
        wsum[lane] = w;
    }
    __syncthreads();
    int warp_off = (wid == 0) ? 0 : wsum[wid - 1];
    int excl = g_boff[blockIdx.x] + warp_off + xs - tsum;

    int e0 = excl;
    int e1 = e0 + v0;
    int e2 = e1 + v1;
    int e3 = e2 + v2;
    if (i0 + 0 < n) { g_rowstart[i0 + 0] = e0; g_cursor[i0 + 0] = e0; }
    if (i0 + 1 < n) { g_rowstart[i0 + 1] = e1; g_cursor[i0 + 1] = e1; }
    if (i0 + 2 < n) { g_rowstart[i0 + 2] = e2; g_cursor[i0 + 2] = e2; }
    if (i0 + 3 < n) { g_rowstart[i0 + 3] = e3; g_cursor[i0 + 3] = e3; }
}

__global__ void fill_kernel(const int* __restrict__ ei, int e, int n) {
    int idx = blockIdx.x * blockDim.x + threadIdx.x;
    if (idx >= e) return;
    int is64 = g_is64;
    int d = edge_val(ei, is64, e + idx);
    int s = edge_val(ei, is64, idx);
    if ((unsigned)d < (unsigned)n && (unsigned)s < (unsigned)n) {
        int pos = atomicAdd(&g_cursor[d], 1);
        g_csr[pos] = s;
    }
}

// Half-warp (16 lanes, one float4 each) per node: gather-sum x rows over the
// node's in-edges, write mean. No atomics; csr index is a broadcast load.
__global__ void agg1_kernel(const float* __restrict__ x, int n) {
    int gt = blockIdx.x * blockDim.x + threadIdx.x;
    int node = gt >> 4;
    int q = gt & 15;
    if (node >= n) return;
    int beg = g_rowstart[node];
    int end = g_rowstart[node + 1];
    const float4* __restrict__ x4 = (const float4*)x;
    float4 acc = make_float4(0.f, 0.f, 0.f, 0.f);
    for (int j = beg; j < end; j++) {
        int s = g_csr[j];
        float4 v = x4[(size_t)s * 16 + q];
        acc.x += v.x; acc.y += v.y; acc.z += v.z; acc.w += v.w;
    }
    int deg = end - beg;
    float inv = 1.0f / (float)(deg > 0 ? deg : 1);
    acc.x *= inv; acc.y *= inv; acc.z *= inv; acc.w *= inv;
    ((float4*)g_agg1)[(size_t)node * 16 + q] = acc;
}

// 2 nodes per thread; packed fma.rn.f32x2 accumulators (64 cols = 32 x f32x2
// per node). Weight LDS.64 broadcasts are amortized over both nodes.
// s = relu(h1).W2_l and r = relu(h1).W2_r computed in-register; h1 never stored.
__global__ __launch_bounds__(128) void h1_kernel(
    const float* __restrict__ x,
    const float* __restrict__ W1l, const float* __restrict__ b1,
    const float* __restrict__ W1r,
    const float* __restrict__ W2l, const float* __restrict__ W2r,
    int n) {
    __shared__ __align__(16) float sWl[F * F];
    __shared__ __align__(16) float sWr[F * F];
    __shared__ __align__(8) float sb1[F], sW2l[F], sW2r[F];
    for (int idx = threadIdx.x; idx < F * F; idx += blockDim.x) {
        sWl[idx] = W1l[idx];
        sWr[idx] = W1r[idx];
    }
    if (threadIdx.x < F) {
        sb1[threadIdx.x]  = b1[threadIdx.x];
        sW2l[threadIdx.x] = W2l[threadIdx.x];
        sW2r[threadIdx.x] = W2r[threadIdx.x];
    }
    __syncthreads();

    int t = blockIdx.x * blockDim.x + threadIdx.x;
    int i0 = t * 2;
    if (i0 >= n) return;
    bool has1 = (i0 + 1 < n);
    int i1 = has1 ? (i0 + 1) : i0;

    const ull* sWl64 = (const ull*)sWl;
    const ull* sWr64 = (const ull*)sWr;

    ull acc0[32], acc1[32];
    #pragma unroll
    for (int j = 0; j < 32; j++) {
        ull b = ((const ull*)sb1)[j];
        acc0[j] = b;
        acc1[j] = b;
    }

    const float4* __restrict__ ag0 = ((const float4*)g_agg1) + (size_t)i0 * 16;
    const float4* __restrict__ ag1 = ((const float4*)g_agg1) + (size_t)i1 * 16;
    const float4* __restrict__ xx0 = ((const float4*)x) + (size_t)i0 * 16;
    const float4* __restrict__ xx1 = ((const float4*)x) + (size_t)i1 * 16;

    #pragma unroll 1
    for (int kc = 0; kc < 16; kc++) {
        float4 a0 = ag0[kc], b0 = xx0[kc];
        float4 a1 = ag1[kc], b1v = xx1[kc];
        float av0[4] = {a0.x, a0.y, a0.z, a0.w};
        float xv0[4] = {b0.x, b0.y, b0.z, b0.w};
        float av1[4] = {a1.x, a1.y, a1.z, a1.w};
        float xv1[4] = {b1v.x, b1v.y, b1v.z, b1v.w};
        #pragma unroll
        for (int kk = 0; kk < 4; kk++) {
            int k = kc * 4 + kk;
            ull apk0 = pk2(av0[kk]), xpk0 = pk2(xv0[kk]);
            ull apk1 = pk2(av1[kk]), xpk1 = pk2(xv1[kk]);
            const ull* wl = sWl64 + k * 32;
            const ull* wr = sWr64 + k * 32;
            #pragma unroll
            for (int j = 0; j < 32; j++) {
                ull w1 = wl[j];
                ull w2 = wr[j];
                acc0[j] = fma2(w1, apk0, acc0[j]);
                acc0[j] = fma2(w2, xpk0, acc0[j]);
                acc1[j] = fma2(w1, apk1, acc1[j]);
                acc1[j] = fma2(w2, xpk1, acc1[j]);
            }
        }
    }

    float s0 = 0.f, r0 = 0.f, s1 = 0.f, r1 = 0.f;
    #pragma unroll
    for (int j = 0; j < 32; j++) {
        float lo, hi;
        upk2(acc0[j], lo, hi);
        float h0 = fmaxf(lo, 0.f), h1v = fmaxf(hi, 0.f);
        s0 += h0 * sW2l[2 * j] + h1v * sW2l[2 * j + 1];
        r0 += h0 * sW2r[2 * j] + h1v * sW2r[2 * j + 1];
        upk2(acc1[j], lo, hi);
        float g0 = fmaxf(lo, 0.f), g1 = fmaxf(hi, 0.f);
        s1 += g0 * sW2l[2 * j] + g1 * sW2l[2 * j + 1];
        r1 += g0 * sW2r[2 * j] + g1 * sW2r[2 * j + 1];
    }
    g_s[i0] = s0;
    g_r[i0] = r0;
    if (has1) { g_s[i1] = s1; g_r[i1] = r1; }
}

// One thread per node: out[i] = mean_j s[j] + b2 + r[i]
__global__ void out_kernel(const float* __restrict__ b2,
                           float* __restrict__ out, int n) {
    int i = blockIdx.x * blockDim.x + threadIdx.x;
    if (i >= n) return;
    int beg = g_rowstart[i];
    int end = g_rowstart[i + 1];
    float sum = 0.f;
    for (int j = beg; j < end; j++) sum += g_s[g_csr[j]];
    int deg = end - beg;
    float inv = 1.0f / (float)(deg > 0 ? deg : 1);
    out[i] = sum * inv + b2[0] + g_r[i];
}

// ---------------------------------------------------------------------------
extern "C" void kernel_launch(void* const* d_in, const int* in_sizes, int n_in,
                              void* d_out, int out_size) {
    const float* x   = (const float*)d_in[0];
    const int*   ei  = (const int*)d_in[1];   // int32 OR int64 (device-detected)
    const float* W1l = (const float*)d_in[2];
    const float* b1  = (const float*)d_in[3];
    const float* W1r = (const float*)d_in[4];
    const float* W2l = (const float*)d_in[5];
    const float* b2  = (const float*)d_in[6];
    const float* W2r = (const float*)d_in[7];
    float* out = (float*)d_out;

    int n = in_sizes[0] / F;      // 100000
    int e = in_sizes[1] / 2;      // 1600000
    int nb = (n + SCAN_CHUNK - 1) / SCAN_CHUNK;   // 25

    detect_kernel<<<1, 32>>>(ei);
    zero_deg_kernel<<<(n + 255) / 256, 256>>>(n);
    count_kernel<<<(e + 255) / 256, 256>>>(ei, e, n);
    scanA_kernel<<<nb, 1024>>>(n);
    scanB_kernel<<<1, 32>>>(nb, n);
    scanC_kernel<<<nb, 1024>>>(n);
    fill_kernel<<<(e + 255) / 256, 256>>>(ei, e, n);
    agg1_kernel<<<(n * 16 + 255) / 256, 256>>>(x, n);
    h1_kernel<<<((n + 1) / 2 + 127) / 128, 128>>>(x, W1l, b1, W1r, W2l, W2r, n);
    out_kernel<<<(n + 255) / 256, 256>>>(b2, out, n);
}

// round 7
// speedup vs baseline: 1.8674x; 1.0132x over previous
#include <cuda_runtime.h>
#include <cuda_bf16.h>

// GraphSAGE, 2-layer, mean aggregation.
//   h1  = relu(mean_agg(x) @ W1_l + b1 + x @ W1_r)
//   out = mean_agg(h1) @ W2_l + b2 + h1 @ W2_r
// Transforms:
//   - layer-2 is 64->1: aggregate SCALARS; h1 never materialized.
//   - layer-1 aggregation via per-call CSR (counting sort), no float atomics.
//   - 7 launches (was 10): dtype-detect inlined per-warp; g_deg zeroing
//     deferred into agg1 (zero-init at load covers call 0); scanB folded
//     into scanC.
//   - count/fill: 4 edges/thread, int4 loads.
//   - h1 GEMM: packed fma.rn.f32x2 + 2 nodes/thread.

#define MAXN 100000
#define MAXE 1600000
#define F 64
#define SCAN_CHUNK 4096
#define MAX_BLOCKS_SCAN 32

typedef unsigned long long ull;

// ---- device scratch (static; allocation is forbidden) ----
__device__ int g_deg[MAXN];            // zero at load; re-zeroed by agg1 each call
__device__ int g_rowstart[MAXN + 1];
__device__ int g_cursor[MAXN];
__device__ int g_csr[MAXE];
__device__ int g_bsum[MAX_BLOCKS_SCAN];
__device__ __align__(16) float g_agg1[(size_t)MAXN * F];
__device__ float g_s[MAXN];
__device__ float g_r[MAXN];

// ---- packed f32x2 helpers -------------------------------------------------
__device__ __forceinline__ ull pk2(float v) {
    ull r; asm("mov.b64 %0, {%1, %1};" : "=l"(r) : "f"(v)); return r;
}
__device__ __forceinline__ ull fma2(ull a, ull b, ull c) {
    ull d; asm("fma.rn.f32x2 %0, %1, %2, %3;" : "=l"(d) : "l"(a), "l"(b), "l"(c));
    return d;
}
__device__ __forceinline__ void upk2(ull v, float& lo, float& hi) {
    asm("mov.b64 {%0, %1}, %2;" : "=f"(lo), "=f"(hi) : "l"(v));
}

// Per-warp dtype detection: viewed as int32, an int64 buffer (ids < 2^31)
// has all odd words zero; an int32 buffer has random node ids there.
// 32 samples: P(all zero | int32, uniform ids over 1e5) ~ 1e-160.
__device__ __forceinline__ int warp_is64(const int* __restrict__ ei) {
    int lane = threadIdx.x & 31;
    int nz = ei[2 * lane + 1];
    #pragma unroll
    for (int d = 16; d; d >>= 1) nz |= __shfl_xor_sync(0xffffffffu, nz, d);
    return nz == 0;
}

// ---------------------------------------------------------------------------
// 4 edges per thread. dst[j] lives at element e+j.
__global__ void count_kernel(const int* __restrict__ ei, int e, int n) {
    int is64 = warp_is64(ei);
    int idx0 = (blockIdx.x * blockDim.x + threadIdx.x) * 4;
    if (idx0 >= e) return;
    int cnt = e - idx0; if (cnt > 4) cnt = 4;
    int d[4];
    if (cnt == 4) {
        if (is64) {
            if (((e + idx0) & 1) == 0) {
                int4 a = *(const int4*)&ei[2 * (e + idx0)];
                int4 b = *(const int4*)&ei[2 * (e + idx0) + 4];
                d[0] = a.x; d[1] = a.z; d[2] = b.x; d[3] = b.z;
            } else {
                #pragma unroll
                for (int i = 0; i < 4; i++) d[i] = ei[2 * (e + idx0 + i)];
            }
        } else {
            if (((e + idx0) & 3) == 0) {
                int4 a = *(const int4*)&ei[e + idx0];
                d[0] = a.x; d[1] = a.y; d[2] = a.z; d[3] = a.w;
            } else {
                #pragma unroll
                for (int i = 0; i < 4; i++) d[i] = ei[e + idx0 + i];
            }
        }
    } else {
        for (int i = 0; i < cnt; i++)
            d[i] = is64 ? ei[2 * (e + idx0 + i)] : ei[e + idx0 + i];
    }
    #pragma unroll
    for (int i = 0; i < 4; i++)
        if (i < cnt && (unsigned)d[i] < (unsigned)n) atomicAdd(&g_deg[d[i]], 1);
}

// ---- scan -----------------------------------------------------------------
// Phase A: per-block sum of a 4096-item chunk of g_deg.
__global__ void scanA_kernel(int n) {
    __shared__ int wsum[32];
    const int tid = threadIdx.x, lane = tid & 31, wid = tid >> 5;
    int i0 = blockIdx.x * SCAN_CHUNK + tid * 4;
    int s = 0;
    if (i0 + 3 < n) {
        int4 v = *(const int4*)&g_deg[i0];
        s = v.x + v.y + v.z + v.w;
    } else {
        for (int j = 0; j < 4; j++) if (i0 + j < n) s += g_deg[i0 + j];
    }
    #pragma unroll
    for (int d = 16; d; d >>= 1) s += __shfl_xor_sync(0xffffffffu, s, d);
    if (lane == 0) wsum[wid] = s;
    __syncthreads();
    if (wid == 0) {
        int w = wsum[lane];
        #pragma unroll
        for (int d = 16; d; d >>= 1) w += __shfl_xor_sync(0xffffffffu, w, d);
        if (lane == 0) g_bsum[blockIdx.x] = w;
    }
}

// Phase C (with B inlined): per-block exclusive scan of its chunk; warp 0
// also scans the <=32 block sums to get this block's global offset.
__global__ void scanC_kernel(int n, int nb) {
    __shared__ int wsum[32];
    __shared__ int s_boff;
    const int tid = threadIdx.x, lane = tid & 31, wid = tid >> 5;
    int base = blockIdx.x * SCAN_CHUNK;
    int i0 = base + tid * 4;
    int v0 = (i0 + 0 < n) ? g_deg[i0 + 0] : 0;
    int v1 = (i0 + 1 < n) ? g_deg[i0 + 1] : 0;
    int v2 = (i0 + 2 < n) ? g_deg[i0 + 2] : 0;
    int v3 = (i0 + 3 < n) ? g_deg[i0 + 3] : 0;
    int tsum = v0 + v1 + v2 + v3;

    int xs = tsum;
    #pragma unroll
    for (int d = 1; d < 32; d <<= 1) {
        int t = __shfl_up_sync(0xffffffffu, xs, d);
        if (lane >= d) xs += t;
    }
    if (lane == 31) wsum[wid] = xs;
    __syncthreads();
    if (wid == 0) {
        // scan per-warp sums
        int w = wsum[lane];
        #pragma unroll
        for (int d = 1; d < 32; d <<= 1) {
            int t = __shfl_up_sync(0xffffffffu, w, d);
            if (lane >= d) w += t;
        }
        wsum[lane] = w;
        // scan block sums (inlined phase B)
        int bv = (lane < nb) ? g_bsum[lane] : 0;
        int bx = bv;
        #pragma unroll
        for (int d = 1; d < 32; d <<= 1) {
            int t = __shfl_up_sync(0xffffffffu, bx, d);
            if (lane >= d) bx += t;
        }
        int myoff = __shfl_sync(0xffffffffu, bx - bv, blockIdx.x);
        int total = __shfl_sync(0xffffffffu, bx, 31);
        if (lane == 0) {
            s_boff = myoff;
            if (blockIdx.x == 0) g_rowstart[n] = total;
        }
    }
    __syncthreads();
    int warp_off = (wid == 0) ? 0 : wsum[wid - 1];
    int excl = s_boff + warp_off + xs - tsum;

    int e0 = excl;
    int e1 = e0 + v0;
    int e2 = e1 + v1;
    int e3 = e2 + v2;
    if (i0 + 0 < n) { g_rowstart[i0 + 0] = e0; g_cursor[i0 + 0] = e0; }
    if (i0 + 1 < n) { g_rowstart[i0 + 1] = e1; g_cursor[i0 + 1] = e1; }
    if (i0 + 2 < n) { g_rowstart[i0 + 2] = e2; g_cursor[i0 + 2] = e2; }
    if (i0 + 3 < n) { g_rowstart[i0 + 3] = e3; g_cursor[i0 + 3] = e3; }
}

// 4 edges per thread, vectorized src+dst loads.
__global__ void fill_kernel(const int* __restrict__ ei, int e, int n) {
    int is64 = warp_is64(ei);
    int idx0 = (blockIdx.x * blockDim.x + threadIdx.x) * 4;
    if (idx0 >= e) return;
    int cnt = e - idx0; if (cnt > 4) cnt = 4;
    int s[4], d[4];
    if (cnt == 4) {
        if (is64) {
            int4 sa = *(const int4*)&ei[2 * idx0];
            int4 sb = *(const int4*)&ei[2 * idx0 + 4];
            s[0] = sa.x; s[1] = sa.z; s[2] = sb.x; s[3] = sb.z;
            if (((e + idx0) & 1) == 0) {
                int4 da = *(const int4*)&ei[2 * (e + idx0)];
                int4 db = *(const int4*)&ei[2 * (e + idx0) + 4];
                d[0] = da.x; d[1] = da.z; d[2] = db.x; d[3] = db.z;
            } else {
                #pragma unroll
                for (int i = 0; i < 4; i++) d[i] = ei[2 * (e + idx0 + i)];
            }
        } else {
            int4 sa = *(const int4*)&ei[idx0];
            s[0] = sa.x; s[1] = sa.y; s[2] = sa.z; s[3] = sa.w;
            if (((e + idx0) & 3) == 0) {
                int4 da = *(const int4*)&ei[e + idx0];
                d[0] = da.x; d[1] = da.y; d[2] = da.z; d[3] = da.w;
            } else {
                #pragma unroll
                for (int i = 0; i < 4; i++) d[i] = ei[e + idx0 + i];
            }
        }
    } else {
        for (int i = 0; i < cnt; i++) {
            s[i] = is64 ? ei[2 * (idx0 + i)] : ei[idx0 + i];
            d[i] = is64 ? ei[2 * (e + idx0 + i)] : ei[e + idx0 + i];
        }
    }
    #pragma unroll
    for (int i = 0; i < 4; i++) {
        if (i < cnt && (unsigned)d[i] < (unsigned)n && (unsigned)s[i] < (unsigned)n) {
            int pos = atomicAdd(&g_cursor[d[i]], 1);
            g_csr[pos] = s[i];
        }
    }
}

// Half-warp (16 lanes, one float4 each) per node: gather-sum x rows over the
// node's in-edges (unroll-by-2, MLP=2), write mean. Also re-zeroes g_deg for
// the next call (its last reader, scanC, has completed).
__global__ void agg1_kernel(const float* __restrict__ x, int n) {
    int gt = blockIdx.x * blockDim.x + threadIdx.x;
    int node = gt >> 4;
    int q = gt & 15;
    if (node >= n) return;
    if (q == 0) g_deg[node] = 0;
    int beg = g_rowstart[node];
    int end = g_rowstart[node + 1];
    const float4* __restrict__ x4 = (const float4*)x;
    float4 acc = make_float4(0.f, 0.f, 0.f, 0.f);
    float4 acc2 = make_float4(0.f, 0.f, 0.f, 0.f);
    int j = beg;
    for (; j + 1 < end; j += 2) {
        int s0 = g_csr[j];
        int s1 = g_csr[j + 1];
        float4 v0 = x4[(size_t)s0 * 16 + q];
        float4 v1 = x4[(size_t)s1 * 16 + q];
        acc.x += v0.x; acc.y += v0.y; acc.z += v0.z; acc.w += v0.w;
        acc2.x += v1.x; acc2.y += v1.y; acc2.z += v1.z; acc2.w += v1.w;
    }
    if (j < end) {
        int s0 = g_csr[j];
        float4 v0 = x4[(size_t)s0 * 16 + q];
        acc.x += v0.x; acc.y += v0.y; acc.z += v0.z; acc.w += v0.w;
    }
    acc.x += acc2.x; acc.y += acc2.y; acc.z += acc2.z; acc.w += acc2.w;
    int deg = end - beg;
    float inv = 1.0f / (float)(deg > 0 ? deg : 1);
    acc.x *= inv; acc.y *= inv; acc.z *= inv; acc.w *= inv;
    ((float4*)g_agg1)[(size_t)node * 16 + q] = acc;
}

// 2 nodes per thread; packed fma.rn.f32x2 accumulators. s/r computed
// in-register; h1 never stored.
__global__ __launch_bounds__(128) void h1_kernel(
    const float* __restrict__ x,
    const float* __restrict__ W1l, const float* __restrict__ b1,
    const float* __restrict__ W1r,
    const float* __restrict__ W2l, const float* __restrict__ W2r,
    int n) {
    __shared__ __align__(16) float sWl[F * F];
    __shared__ __align__(16) float sWr[F * F];
    __shared__ __align__(8) float sb1[F], sW2l[F], sW2r[F];
    for (int idx = threadIdx.x; idx < F * F; idx += blockDim.x) {
        sWl[idx] = W1l[idx];
        sWr[idx] = W1r[idx];
    }
    if (threadIdx.x < F) {
        sb1[threadIdx.x]  = b1[threadIdx.x];
        sW2l[threadIdx.x] = W2l[threadIdx.x];
        sW2r[threadIdx.x] = W2r[threadIdx.x];
    }
    __syncthreads();

    int t = blockIdx.x * blockDim.x + threadIdx.x;
    int i0 = t * 2;
    if (i0 >= n) return;
    bool has1 = (i0 + 1 < n);
    int i1 = has1 ? (i0 + 1) : i0;

    const ull* sWl64 = (const ull*)sWl;
    const ull* sWr64 = (const ull*)sWr;

    ull acc0[32], acc1[32];
    #pragma unroll
    for (int j = 0; j < 32; j++) {
        ull b = ((const ull*)sb1)[j];
        acc0[j] = b;
        acc1[j] = b;
    }

    const float4* __restrict__ ag0 = ((const float4*)g_agg1) + (size_t)i0 * 16;
    const float4* __restrict__ ag1 = ((const float4*)g_agg1) + (size_t)i1 * 16;
    const float4* __restrict__ xx0 = ((const float4*)x) + (size_t)i0 * 16;
    const float4* __restrict__ xx1 = ((const float4*)x) + (size_t)i1 * 16;

    #pragma unroll 1
    for (int kc = 0; kc < 16; kc++) {
        float4 a0 = ag0[kc], b0 = xx0[kc];
        float4 a1 = ag1[kc], b1v = xx1[kc];
        float av0[4] = {a0.x, a0.y, a0.z, a0.w};
        float xv0[4] = {b0.x, b0.y, b0.z, b0.w};
        float av1[4] = {a1.x, a1.y, a1.z, a1.w};
        float xv1[4] = {b1v.x, b1v.y, b1v.z, b1v.w};
        #pragma unroll
        for (int kk = 0; kk < 4; kk++) {
            int k = kc * 4 + kk;
            ull apk0 = pk2(av0[kk]), xpk0 = pk2(xv0[kk]);
            ull apk1 = pk2(av1[kk]), xpk1 = pk2(xv1[kk]);
            const ull* wl = sWl64 + k * 32;
            const ull* wr = sWr64 + k * 32;
            #pragma unroll
            for (int j = 0; j < 32; j++) {
                ull w1 = wl[j];
                ull w2 = wr[j];
                acc0[j] = fma2(w1, apk0, acc0[j]);
                acc0[j] = fma2(w2, xpk0, acc0[j]);
                acc1[j] = fma2(w1, apk1, acc1[j]);
                acc1[j] = fma2(w2, xpk1, acc1[j]);
            }
        }
    }

    float s0 = 0.f, r0 = 0.f, s1 = 0.f, r1 = 0.f;
    #pragma unroll
    for (int j = 0; j < 32; j++) {
        float lo, hi;
        upk2(acc0[j], lo, hi);
        float h0 = fmaxf(lo, 0.f), h1v = fmaxf(hi, 0.f);
        s0 += h0 * sW2l[2 * j] + h1v * sW2l[2 * j + 1];
        r0 += h0 * sW2r[2 * j] + h1v * sW2r[2 * j + 1];
        upk2(acc1[j], lo, hi);
        float g0 = fmaxf(lo, 0.f), g1 = fmaxf(hi, 0.f);
        s1 += g0 * sW2l[2 * j] + g1 * sW2l[2 * j + 1];
        r1 += g0 * sW2r[2 * j] + g1 * sW2r[2 * j + 1];
    }
    g_s[i0] = s0;
    g_r[i0] = r0;
    if (has1) { g_s[i1] = s1; g_r[i1] = r1; }
}

// One thread per node: out[i] = mean_j s[j] + b2 + r[i]  (unroll-by-2)
__global__ void out_kernel(const float* __restrict__ b2,
                           float* __restrict__ out, int n) {
    int i = blockIdx.x * blockDim.x + threadIdx.x;
    if (i >= n) return;
    int beg = g_rowstart[i];
    int end = g_rowstart[i + 1];
    float sum = 0.f, sum2 = 0.f;
    int j = beg;
    for (; j + 1 < end; j += 2) {
        sum  += g_s[g_csr[j]];
        sum2 += g_s[g_csr[j + 1]];
    }
    if (j < end) sum += g_s[g_csr[j]];
    sum += sum2;
    int deg = end - beg;
    float inv = 1.0f / (float)(deg > 0 ? deg : 1);
    out[i] = sum * inv + b2[0] + g_r[i];
}

// ---------------------------------------------------------------------------
extern "C" void kernel_launch(void* const* d_in, const int* in_sizes, int n_in,
                              void* d_out, int out_size) {
    const float* x   = (const float*)d_in[0];
    const int*   ei  = (const int*)d_in[1];   // int32 OR int64 (warp-detected)
    const float* W1l = (const float*)d_in[2];
    const float* b1  = (const float*)d_in[3];
    const float* W1r = (const float*)d_in[4];
    const float* W2l = (const float*)d_in[5];
    const float* b2  = (const float*)d_in[6];
    const float* W2r = (const float*)d_in[7];
    float* out = (float*)d_out;

    int n = in_sizes[0] / F;      // 100000
    int e = in_sizes[1] / 2;      // 1600000
    int nb = (n + SCAN_CHUNK - 1) / SCAN_CHUNK;   // 25
    int et = (e + 3) / 4;         // edge threads (4 edges each)

    count_kernel<<<(et + 255) / 256, 256>>>(ei, e, n);
    scanA_kernel<<<nb, 1024>>>(n);
    scanC_kernel<<<nb, 1024>>>(n, nb);
    fill_kernel<<<(et + 255) / 256, 256>>>(ei, e, n);
    agg1_kernel<<<(n * 16 + 255) / 256, 256>>>(x, n);
    h1_kernel<<<((n + 1) / 2 + 127) / 128, 128>>>(x, W1l, b1, W1r, W2l, W2r, n);
    out_kernel<<<(n + 255) / 256, 256>>>(b2, out, n);
}